// round 13
// baseline (speedup 1.0000x reference)
#include <cuda_runtime.h>
#include <cuda_fp16.h>

#define NN 50000
#define NE 500000
#define NB 2048            // distance table bins over [0, 8)

typedef unsigned long long u64;

// ---- persistent device scratch (zero-initialized at module load) ----
__device__ float  g_Wsg[64 * 256];    // W_src @ W_gate (natural order)
__device__ float  g_Wdg[64 * 256];    // W_dst @ W_gate
__device__ __half g_Wg8h[8 * 256];    // W_enc @ W_gate, packed half2 [(k*4+j)*32+l]
__device__ float  g_bgf[256];         // fused bias — folded into GsP
__device__ __half g_GsP[NN * 256];    // per-node src-side gate pre + bias
__device__ __half g_Dn[NN * 512];     // per-node dst-side: [0:256)=Gd, [256:512)=z1x,z1y,z1z,z0
__device__ __half g_T[NB * 256];      // dist gate table, lane-interleaved [bin*256 + l*8 + j*2 + h]
__device__ float  g_accP[NN * 256];   // acc: [0:128)=lane*4+{s0,s1,vx0,vx1}; [128:256)={vy0,vy1,vz0,vz1}

// ---- packed f32x2 helpers ----
__device__ __forceinline__ u64 pk(float x, float y) {
    u64 r; asm("mov.b64 %0,{%1,%2};" : "=l"(r) : "f"(x), "f"(y)); return r;
}
__device__ __forceinline__ float2 upk(u64 v) {
    float2 f; asm("mov.b64 {%0,%1},%2;" : "=f"(f.x), "=f"(f.y) : "l"(v)); return f;
}
__device__ __forceinline__ u64 ffma2(u64 a, u64 b, u64 c) {
    u64 r; asm("fma.rn.f32x2 %0,%1,%2,%3;" : "=l"(r) : "l"(a), "l"(b), "l"(c)); return r;
}
__device__ __forceinline__ u64 fmul2(u64 a, u64 b) {
    u64 r; asm("mul.rn.f32x2 %0,%1,%2;" : "=l"(r) : "l"(a), "l"(b)); return r;
}
__device__ __forceinline__ u64 h2f(__half2 h) {
    float2 f = __half22float2(h); return pk(f.x, f.y);
}
__device__ __forceinline__ __half2 u2h(unsigned v) {
    return *reinterpret_cast<__half2*>(&v);
}
__device__ __forceinline__ void red4(float* p, u64 ab, u64 cd) {
    float2 a = upk(ab), c = upk(cd);
    asm volatile("red.global.add.v4.f32 [%0], {%1,%2,%3,%4};"
                 :: "l"(p), "f"(a.x), "f"(a.y), "f"(c.x), "f"(c.y) : "memory");
}

// ---------------------------------------------------------------------------
// 1) fold small weight matrices
// ---------------------------------------------------------------------------
__global__ void prep_weights(const float* __restrict__ W_src, const float* __restrict__ W_dst,
                             const float* __restrict__ W_enc, const float* __restrict__ W_gate,
                             const float* __restrict__ b_gate, const float* __restrict__ b_enc,
                             const float* __restrict__ b_src, const float* __restrict__ b_dst) {
    int idx = blockIdx.x * blockDim.x + threadIdx.x;
    if (idx < 16384) {
        int k = idx >> 8, c = idx & 255;
        float s = 0.f;
        #pragma unroll 8
        for (int t = 0; t < 64; t++) s += W_src[k * 64 + t] * W_gate[t * 256 + c];
        g_Wsg[idx] = s;
    } else if (idx < 32768) {
        int t0 = idx - 16384;
        int k = t0 >> 8, c = t0 & 255;
        float s = 0.f;
        #pragma unroll 8
        for (int t = 0; t < 64; t++) s += W_dst[k * 64 + t] * W_gate[t * 256 + c];
        g_Wdg[t0] = s;
    } else if (idx < 34816) {
        int t0 = idx - 32768;
        int k = t0 >> 8, c = t0 & 255;
        float s = 0.f;
        #pragma unroll 8
        for (int t = 0; t < 64; t++) s += W_enc[k * 64 + t] * W_gate[t * 256 + c];
        int j = c >> 6, l = (c & 63) >> 1, h = c & 1;
        g_Wg8h[((k * 4 + j) * 32 + l) * 2 + h] = __float2half(s);
    } else if (idx < 35072) {
        int c = idx - 34816;
        float s = b_gate[c];
        for (int t = 0; t < 64; t++) s += (b_enc[t] + b_src[t] + b_dst[t]) * W_gate[t * 256 + c];
        g_bgf[c] = s;
    }
}

// ---------------------------------------------------------------------------
// 1b) distance gate table: T[bin][cp] = sum_k rbf_k(bin/256) * Wg8[k][cp]
// ---------------------------------------------------------------------------
__global__ void table_kernel() {
    int idx = blockIdx.x * blockDim.x + threadIdx.x;
    if (idx >= NB * 256) return;
    int b = idx >> 8, cp = idx & 255;
    int l = cp >> 3, j = (cp >> 1) & 3, h = cp & 1;
    float dd = (float)b * (1.0f / 256.0f);
    float s = 0.f;
    #pragma unroll
    for (int k = 0; k < 8; k++) {
        float u = dd * 4.f - (8.f / 7.f) * (float)k;
        s += expf(-u * u) * __half2float(g_Wg8h[((k * 4 + j) * 32 + l) * 2 + h]);
    }
    g_T[idx] = __float2half(s);
}

// ---------------------------------------------------------------------------
// 2) node precompute: one thread computes BOTH Gs[c] (+bias) and Gd[c] for
//    32 nodes (16 f32x2 pairs). Each es LDS.64 broadcast feeds 2 FFMA2.
// ---------------------------------------------------------------------------
__global__ __launch_bounds__(256) void node_pre(const float* __restrict__ emb) {
    __shared__ float es[64][34];   // [channel][node], 34 floats/row = 136B (8B-aligned)
    int base = blockIdx.x * 32;
    for (int i = threadIdx.x; i < 32 * 64; i += 256) {
        int n = i >> 6, c = i & 63;            // coalesced emb read
        es[c][n] = (base + n < NN) ? emb[(size_t)(base + n) * 64 + c] : 0.f;
    }
    __syncthreads();
    int c = threadIdx.x;                        // output channel 0..255
    float bias = g_bgf[c];
    u64 as[16], ad[16];
    #pragma unroll
    for (int p = 0; p < 16; p++) { as[p] = pk(bias, bias); ad[p] = pk(0.f, 0.f); }
    for (int k = 0; k < 64; k++) {
        float ws = g_Wsg[k * 256 + c];
        float wd = g_Wdg[k * 256 + c];
        u64 ws2 = pk(ws, ws), wd2 = pk(wd, wd);
        const u64* row = (const u64*)&es[k][0];  // broadcast, 8B-aligned
        #pragma unroll
        for (int p = 0; p < 16; p++) {
            u64 e2 = row[p];
            as[p] = ffma2(ws2, e2, as[p]);
            ad[p] = ffma2(wd2, e2, ad[p]);
        }
    }
    #pragma unroll
    for (int p = 0; p < 16; p++) {
        float2 vs = upk(as[p]), vd = upk(ad[p]);
        int n0 = base + 2 * p;
        if (n0 < NN) {
            g_GsP[(size_t)n0 * 256 + c] = __float2half(vs.x);
            g_Dn[(size_t)n0 * 512 + c]  = __float2half(vd.x);
        }
        if (n0 + 1 < NN) {
            g_GsP[(size_t)(n0 + 1) * 256 + c] = __float2half(vs.y);
            g_Dn[(size_t)(n0 + 1) * 512 + c]  = __float2half(vd.y);
        }
    }
}

// ---------------------------------------------------------------------------
// 3) fused: zero accumulator + pack z0/z1 -> g_Dn[256:512)
// ---------------------------------------------------------------------------
__global__ void zero_convert(const float* __restrict__ z0, const float* __restrict__ z1) {
    const int T0 = NN * 64;            // float4 zeroes for acc
    const int T1 = T0 + NN * 128;      // half2 packs for z
    int i = blockIdx.x * blockDim.x + threadIdx.x;
    int stride = gridDim.x * blockDim.x;
    __half2* Dn2 = (__half2*)g_Dn;
    for (; i < T1; i += stride) {
        if (i < T0) {
            ((float4*)g_accP)[i] = make_float4(0.f, 0.f, 0.f, 0.f);
        } else {
            int j = i - T0;
            int n = j >> 7, p = j & 127;
            int t = p >> 5, l = p & 31;
            float2 v = (t < 3) ? ((const float2*)z1)[n * 96 + t * 32 + l]
                               : ((const float2*)z0)[n * 32 + l];
            Dn2[(size_t)n * 256 + 128 + t * 32 + l] = __float22half2_rn(v);
        }
    }
}

// ---------------------------------------------------------------------------
// 4) edge kernel (UNCHANGED from R12 best): table-based gate, unroll-2
//    ping-pong, half2 gathers, f32x2 message math, red.v4 scatter.
// ---------------------------------------------------------------------------
struct EB {
    __half2 cg[12];       // 4×Gs+bias, 4×Gd, z1x,z1y,z1z,z0
    __half2 tl[4], th[4]; // dist table rows (low bin, high bin), group-per-half2
    float rx, ry, rz, frac;
};

__device__ __forceinline__ void fill_buf(EB& b, int s, int d,
                                         float rx, float ry, float rz, int lane) {
    b.rx = rx; b.ry = ry; b.rz = rz;
    float dd = sqrtf(fmaf(rx, rx, fmaf(ry, ry, rz * rz)));
    float bf = dd * 256.0f;
    int ib = (int)bf; if (ib > NB - 2) ib = NB - 2;
    b.frac = bf - (float)ib;
    const uint2* Tl = (const uint2*)(g_T + (size_t)ib * 256 + lane * 8);
    const uint2* Th = (const uint2*)(g_T + (size_t)(ib + 1) * 256 + lane * 8);
    uint2 a0 = __ldg(Tl), a1 = __ldg(Tl + 1);
    uint2 c0 = __ldg(Th), c1 = __ldg(Th + 1);
    b.tl[0] = u2h(a0.x); b.tl[1] = u2h(a0.y); b.tl[2] = u2h(a1.x); b.tl[3] = u2h(a1.y);
    b.th[0] = u2h(c0.x); b.th[1] = u2h(c0.y); b.th[2] = u2h(c1.x); b.th[3] = u2h(c1.y);
    const __half2* Gs2 = (const __half2*)g_GsP;
    const __half2* Dn2 = (const __half2*)g_Dn;
    #pragma unroll
    for (int q = 0; q < 4; q++) b.cg[q] = __ldg(&Gs2[(size_t)s * 128 + q * 32 + lane]);
    #pragma unroll
    for (int q = 0; q < 8; q++) b.cg[4 + q] = __ldg(&Dn2[(size_t)d * 256 + q * 32 + lane]);
}

__device__ __forceinline__ void do_edge(const EB& b, int s, int lane) {
    float rx = b.rx, ry = b.ry, rz = b.rz;
    float d2r = fmaf(rx, rx, fmaf(ry, ry, rz * rz));
    float inv = rsqrtf(fmaf(12.25f, d2r, 1.f));
    float hx = 3.5f * rx * inv, hy = 3.5f * ry * inv, hz = 3.5f * rz * inv;

    __half2 fr = __float2half2_rn(b.frac);
    u64 g[4];
    #pragma unroll
    for (int j = 0; j < 4; j++) {
        __half2 dist = __hfma2(fr, __hsub2(b.th[j], b.tl[j]), b.tl[j]);
        __half2 gh = __hadd2(__hadd2(b.cg[j], b.cg[4 + j]), dist);
        g[j] = h2f(gh);
    }

    u64 ZA = h2f(b.cg[8]), ZB = h2f(b.cg[9]), ZC = h2f(b.cg[10]), Z0 = h2f(b.cg[11]);
    u64 HX = pk(hx, hx), HY = pk(hy, hy), HZ = pk(hz, hz);

    u64 dot  = ffma2(HZ, ZC, ffma2(HY, ZB, fmul2(HX, ZA)));
    u64 smsg = ffma2(g[1], dot, fmul2(g[0], Z0));
    u64 tt   = fmul2(g[3], Z0);
    u64 vx   = ffma2(HX, tt, fmul2(g[2], ZA));
    u64 vy   = ffma2(HY, tt, fmul2(g[2], ZB));
    u64 vz   = ffma2(HZ, tt, fmul2(g[2], ZC));

    float* base = g_accP + (size_t)s * 256 + lane * 4;
    red4(base, smsg, vx);
    red4(base + 128, vy, vz);
}

__global__ __launch_bounds__(256, 3) void edge_kernel(const int* __restrict__ src,
                                                      const int* __restrict__ dst,
                                                      const float* __restrict__ r_ij) {
    const int lane = threadIdx.x & 31;
    const int warp = blockIdx.x * 8 + (threadIdx.x >> 5);
    const int nwarp = gridDim.x * 8;

    EB A, B;
    int e0 = warp, s0 = 0;
    if (e0 < NE) {
        s0 = __ldg(src + e0);
        int d0 = __ldg(dst + e0);
        float rx = __ldg(r_ij + 3 * e0), ry = __ldg(r_ij + 3 * e0 + 1), rz = __ldg(r_ij + 3 * e0 + 2);
        fill_buf(A, s0, d0, rx, ry, rz, lane);
    }
    int e1 = e0 + nwarp, s1 = 0, d1 = 0;
    float r1x = 0.f, r1y = 0.f, r1z = 0.f;
    if (e1 < NE) {
        s1 = __ldg(src + e1); d1 = __ldg(dst + e1);
        r1x = __ldg(r_ij + 3 * e1); r1y = __ldg(r_ij + 3 * e1 + 1); r1z = __ldg(r_ij + 3 * e1 + 2);
    }

    while (e0 < NE) {
        // stage 1: fill B for e1; fetch idx+r for e2; compute e0
        int e2 = e1 + nwarp, s2 = 0, d2 = 0;
        float r2x = 0.f, r2y = 0.f, r2z = 0.f;
        if (e1 < NE) fill_buf(B, s1, d1, r1x, r1y, r1z, lane);
        if (e2 < NE) {
            s2 = __ldg(src + e2); d2 = __ldg(dst + e2);
            r2x = __ldg(r_ij + 3 * e2); r2y = __ldg(r_ij + 3 * e2 + 1); r2z = __ldg(r_ij + 3 * e2 + 2);
        }
        do_edge(A, s0, lane);
        if (e1 >= NE) break;

        // stage 2: fill A for e2; fetch idx+r for e3; compute e1
        int e3 = e2 + nwarp, s3 = 0, d3 = 0;
        float r3x = 0.f, r3y = 0.f, r3z = 0.f;
        if (e2 < NE) fill_buf(A, s2, d2, r2x, r2y, r2z, lane);
        if (e3 < NE) {
            s3 = __ldg(src + e3); d3 = __ldg(dst + e3);
            r3x = __ldg(r_ij + 3 * e3); r3y = __ldg(r_ij + 3 * e3 + 1); r3z = __ldg(r_ij + 3 * e3 + 2);
        }
        do_edge(B, s1, lane);

        e0 = e2; s0 = s2;
        e1 = e3; s1 = s3; d1 = d3; r1x = r3x; r1y = r3y; r1z = r3z;
    }
}

// ---------------------------------------------------------------------------
// 5) final: out0 = acc_s @ W_s ; out1[:,i,:] = acc_v_i @ W_v
//    acc idx for (m,k): ((m>=2)?128:0) + 4*(k>>1) + ((m==1||m==3)?2:0) + (k&1)
// ---------------------------------------------------------------------------
__global__ __launch_bounds__(256) void final_kernel(const float* __restrict__ W_s,
                                                    const float* __restrict__ W_v,
                                                    float* __restrict__ out) {
    __shared__ float as[16][256];
    int base = blockIdx.x * 16;
    for (int i = threadIdx.x; i < 16 * 256; i += 256)
        as[i >> 8][i & 255] = g_accP[(size_t)base * 256 + i];
    __syncthreads();
    int o = threadIdx.x;
    int c = o & 63;
    int m = (o < 64) ? 0 : 1 + ((o - 64) >> 6);
    const float* W = (o < 64) ? W_s : W_v;
    int off = ((m >= 2) ? 128 : 0) + ((m == 1 || m == 3) ? 2 : 0);
    float a[16];
    #pragma unroll
    for (int n = 0; n < 16; n++) a[n] = 0.f;
    for (int k = 0; k < 64; k++) {
        float wv = W[k * 64 + c];
        int idx = off + 4 * (k >> 1) + (k & 1);
        #pragma unroll
        for (int n = 0; n < 16; n++) a[n] += as[n][idx] * wv;
    }
    if (m == 0) {
        #pragma unroll
        for (int n = 0; n < 16; n++) out[(base + n) * 64 + c] = a[n];
    } else {
        int i = m - 1;
        #pragma unroll
        for (int n = 0; n < 16; n++)
            out[NN * 64 + ((base + n) * 3 + i) * 64 + c] = a[n];
    }
}

// ---------------------------------------------------------------------------
extern "C" void kernel_launch(void* const* d_in, const int* in_sizes, int n_in,
                              void* d_out, int out_size) {
    const int*   src    = (const int*)d_in[0];
    const int*   dst    = (const int*)d_in[1];
    const float* r_ij   = (const float*)d_in[2];
    const float* z_0    = (const float*)d_in[3];
    const float* z_1    = (const float*)d_in[4];
    const float* emb    = (const float*)d_in[5];
    const float* W_enc  = (const float*)d_in[6];
    const float* b_enc  = (const float*)d_in[7];
    const float* W_src  = (const float*)d_in[8];
    const float* b_src  = (const float*)d_in[9];
    const float* W_dst  = (const float*)d_in[10];
    const float* b_dst  = (const float*)d_in[11];
    const float* W_gate = (const float*)d_in[12];
    const float* b_gate = (const float*)d_in[13];
    const float* W_s    = (const float*)d_in[14];
    const float* W_v    = (const float*)d_in[15];
    float* out = (float*)d_out;

    zero_convert<<<2048, 256>>>(z_0, z_1);
    prep_weights<<<137, 256>>>(W_src, W_dst, W_enc, W_gate, b_gate, b_enc, b_src, b_dst);
    table_kernel<<<(NB * 256 + 255) / 256, 256>>>();
    node_pre<<<(NN + 31) / 32, 256>>>(emb);
    edge_kernel<<<888, 256>>>(src, dst, r_ij);
    final_kernel<<<NN / 16, 256>>>(W_s, W_v, out);
}

// round 17
// speedup vs baseline: 1.3580x; 1.3580x over previous
#include <cuda_runtime.h>
#include <cuda_fp16.h>

#define NN 50000
#define NE 500000
#define NB 2048            // distance table bins over [0, 8)

typedef unsigned long long u64;

// ---- persistent device scratch (zero-initialized at module load) ----
__device__ float  g_Wsg[64 * 256];    // W_src @ W_gate (natural order)
__device__ float  g_Wdg[64 * 256];    // W_dst @ W_gate
__device__ __half g_Wg8h[8 * 256];    // W_enc @ W_gate, packed half2 [(k*4+j)*32+l]
__device__ float  g_bgf[256];         // fused bias — folded into GsP
__device__ __half g_GsP[NN * 256];    // per-node src-side gate pre + bias
__device__ __half g_Dn[NN * 512];     // per-node dst-side: [0:256)=Gd, [256:512)=z1x,z1y,z1z,z0
__device__ __half g_T[NB * 256];      // dist gate table, lane-interleaved [bin*256 + l*8 + j*2 + h]
__device__ float  g_accP[NN * 256];   // acc: [0:128)=lane*4+{s0,s1,vx0,vx1}; [128:256)={vy0,vy1,vz0,vz1}

// ---- packed f32x2 helpers ----
__device__ __forceinline__ u64 pk(float x, float y) {
    u64 r; asm("mov.b64 %0,{%1,%2};" : "=l"(r) : "f"(x), "f"(y)); return r;
}
__device__ __forceinline__ float2 upk(u64 v) {
    float2 f; asm("mov.b64 {%0,%1},%2;" : "=f"(f.x), "=f"(f.y) : "l"(v)); return f;
}
__device__ __forceinline__ u64 ffma2(u64 a, u64 b, u64 c) {
    u64 r; asm("fma.rn.f32x2 %0,%1,%2,%3;" : "=l"(r) : "l"(a), "l"(b), "l"(c)); return r;
}
__device__ __forceinline__ u64 fmul2(u64 a, u64 b) {
    u64 r; asm("mul.rn.f32x2 %0,%1,%2;" : "=l"(r) : "l"(a), "l"(b)); return r;
}
__device__ __forceinline__ u64 h2f(__half2 h) {
    float2 f = __half22float2(h); return pk(f.x, f.y);
}
__device__ __forceinline__ __half2 u2h(unsigned v) {
    return *reinterpret_cast<__half2*>(&v);
}
__device__ __forceinline__ void red4(float* p, u64 ab, u64 cd) {
    float2 a = upk(ab), c = upk(cd);
    asm volatile("red.global.add.v4.f32 [%0], {%1,%2,%3,%4};"
                 :: "l"(p), "f"(a.x), "f"(a.y), "f"(c.x), "f"(c.y) : "memory");
}

// ---------------------------------------------------------------------------
// 1) fold small weight matrices
// ---------------------------------------------------------------------------
__global__ void prep_weights(const float* __restrict__ W_src, const float* __restrict__ W_dst,
                             const float* __restrict__ W_enc, const float* __restrict__ W_gate,
                             const float* __restrict__ b_gate, const float* __restrict__ b_enc,
                             const float* __restrict__ b_src, const float* __restrict__ b_dst) {
    int idx = blockIdx.x * blockDim.x + threadIdx.x;
    if (idx < 16384) {
        int k = idx >> 8, c = idx & 255;
        float s = 0.f;
        #pragma unroll 8
        for (int t = 0; t < 64; t++) s += W_src[k * 64 + t] * W_gate[t * 256 + c];
        g_Wsg[idx] = s;
    } else if (idx < 32768) {
        int t0 = idx - 16384;
        int k = t0 >> 8, c = t0 & 255;
        float s = 0.f;
        #pragma unroll 8
        for (int t = 0; t < 64; t++) s += W_dst[k * 64 + t] * W_gate[t * 256 + c];
        g_Wdg[t0] = s;
    } else if (idx < 34816) {
        int t0 = idx - 32768;
        int k = t0 >> 8, c = t0 & 255;
        float s = 0.f;
        #pragma unroll 8
        for (int t = 0; t < 64; t++) s += W_enc[k * 64 + t] * W_gate[t * 256 + c];
        int j = c >> 6, l = (c & 63) >> 1, h = c & 1;
        g_Wg8h[((k * 4 + j) * 32 + l) * 2 + h] = __float2half(s);
    } else if (idx < 35072) {
        int c = idx - 34816;
        float s = b_gate[c];
        for (int t = 0; t < 64; t++) s += (b_enc[t] + b_src[t] + b_dst[t]) * W_gate[t * 256 + c];
        g_bgf[c] = s;
    }
}

// ---------------------------------------------------------------------------
// 1b) distance gate table: T[bin][cp] = sum_k rbf_k(bin/256) * Wg8[k][cp]
// ---------------------------------------------------------------------------
__global__ void table_kernel() {
    int idx = blockIdx.x * blockDim.x + threadIdx.x;
    if (idx >= NB * 256) return;
    int b = idx >> 8, cp = idx & 255;
    int l = cp >> 3, j = (cp >> 1) & 3, h = cp & 1;
    float dd = (float)b * (1.0f / 256.0f);
    float s = 0.f;
    #pragma unroll
    for (int k = 0; k < 8; k++) {
        float u = dd * 4.f - (8.f / 7.f) * (float)k;
        s += expf(-u * u) * __half2float(g_Wg8h[((k * 4 + j) * 32 + l) * 2 + h]);
    }
    g_T[idx] = __float2half(s);
}

// ---------------------------------------------------------------------------
// 2) node precompute (R12 shape + f32x2): 512 threads, thread owns one
//    matrix-channel; 16 nodes as 8 f32x2 pairs -> 8 u64 accums (low regs).
// ---------------------------------------------------------------------------
__global__ __launch_bounds__(512) void node_pre(const float* __restrict__ emb) {
    __shared__ float es[64][18];   // [channel][node], 18 floats/row = 72B (8B-aligned)
    int base = blockIdx.x * 16;    // NN % 16 == 0 -> no bounds checks
    for (int i = threadIdx.x; i < 16 * 64; i += 512) {
        int n = i >> 6, c = i & 63;
        es[c][n] = emb[(size_t)(base + n) * 64 + c];
    }
    __syncthreads();
    int t = threadIdx.x;
    int c = t & 255;
    const float* W = (t < 256) ? g_Wsg : g_Wdg;
    float bias = (t < 256) ? g_bgf[c] : 0.f;
    u64 a[8];
    #pragma unroll
    for (int p = 0; p < 8; p++) a[p] = pk(bias, bias);
    for (int k = 0; k < 64; k++) {
        float wv = W[k * 256 + c];
        u64 w2 = pk(wv, wv);
        const u64* row = (const u64*)&es[k][0];   // broadcast LDS.64
        #pragma unroll
        for (int p = 0; p < 8; p++) a[p] = ffma2(w2, row[p], a[p]);
    }
    __half* G = (t < 256) ? g_GsP : g_Dn;
    int stride = (t < 256) ? 256 : 512;
    #pragma unroll
    for (int p = 0; p < 8; p++) {
        float2 v = upk(a[p]);
        int n0 = base + 2 * p;
        G[(size_t)n0 * stride + c]       = __float2half(v.x);
        G[(size_t)(n0 + 1) * stride + c] = __float2half(v.y);
    }
}

// ---------------------------------------------------------------------------
// 3) fused: zero accumulator + pack z0/z1 -> g_Dn[256:512)
// ---------------------------------------------------------------------------
__global__ void zero_convert(const float* __restrict__ z0, const float* __restrict__ z1) {
    const int T0 = NN * 64;            // float4 zeroes for acc
    const int T1 = T0 + NN * 128;      // half2 packs for z
    int i = blockIdx.x * blockDim.x + threadIdx.x;
    int stride = gridDim.x * blockDim.x;
    __half2* Dn2 = (__half2*)g_Dn;
    for (; i < T1; i += stride) {
        if (i < T0) {
            ((float4*)g_accP)[i] = make_float4(0.f, 0.f, 0.f, 0.f);
        } else {
            int j = i - T0;
            int n = j >> 7, p = j & 127;
            int t = p >> 5, l = p & 31;
            float2 v = (t < 3) ? ((const float2*)z1)[n * 96 + t * 32 + l]
                               : ((const float2*)z0)[n * 32 + l];
            Dn2[(size_t)n * 256 + 128 + t * 32 + l] = __float22half2_rn(v);
        }
    }
}

// ---------------------------------------------------------------------------
// 4) edge kernel (UNCHANGED from R12 best): table-based gate, unroll-2
//    ping-pong, half2 gathers, f32x2 message math, red.v4 scatter.
// ---------------------------------------------------------------------------
struct EB {
    __half2 cg[12];       // 4×Gs+bias, 4×Gd, z1x,z1y,z1z,z0
    __half2 tl[4], th[4]; // dist table rows (low bin, high bin), group-per-half2
    float rx, ry, rz, frac;
};

__device__ __forceinline__ void fill_buf(EB& b, int s, int d,
                                         float rx, float ry, float rz, int lane) {
    b.rx = rx; b.ry = ry; b.rz = rz;
    float dd = sqrtf(fmaf(rx, rx, fmaf(ry, ry, rz * rz)));
    float bf = dd * 256.0f;
    int ib = (int)bf; if (ib > NB - 2) ib = NB - 2;
    b.frac = bf - (float)ib;
    const uint2* Tl = (const uint2*)(g_T + (size_t)ib * 256 + lane * 8);
    const uint2* Th = (const uint2*)(g_T + (size_t)(ib + 1) * 256 + lane * 8);
    uint2 a0 = __ldg(Tl), a1 = __ldg(Tl + 1);
    uint2 c0 = __ldg(Th), c1 = __ldg(Th + 1);
    b.tl[0] = u2h(a0.x); b.tl[1] = u2h(a0.y); b.tl[2] = u2h(a1.x); b.tl[3] = u2h(a1.y);
    b.th[0] = u2h(c0.x); b.th[1] = u2h(c0.y); b.th[2] = u2h(c1.x); b.th[3] = u2h(c1.y);
    const __half2* Gs2 = (const __half2*)g_GsP;
    const __half2* Dn2 = (const __half2*)g_Dn;
    #pragma unroll
    for (int q = 0; q < 4; q++) b.cg[q] = __ldg(&Gs2[(size_t)s * 128 + q * 32 + lane]);
    #pragma unroll
    for (int q = 0; q < 8; q++) b.cg[4 + q] = __ldg(&Dn2[(size_t)d * 256 + q * 32 + lane]);
}

__device__ __forceinline__ void do_edge(const EB& b, int s, int lane) {
    float rx = b.rx, ry = b.ry, rz = b.rz;
    float d2r = fmaf(rx, rx, fmaf(ry, ry, rz * rz));
    float inv = rsqrtf(fmaf(12.25f, d2r, 1.f));
    float hx = 3.5f * rx * inv, hy = 3.5f * ry * inv, hz = 3.5f * rz * inv;

    __half2 fr = __float2half2_rn(b.frac);
    u64 g[4];
    #pragma unroll
    for (int j = 0; j < 4; j++) {
        __half2 dist = __hfma2(fr, __hsub2(b.th[j], b.tl[j]), b.tl[j]);
        __half2 gh = __hadd2(__hadd2(b.cg[j], b.cg[4 + j]), dist);
        g[j] = h2f(gh);
    }

    u64 ZA = h2f(b.cg[8]), ZB = h2f(b.cg[9]), ZC = h2f(b.cg[10]), Z0 = h2f(b.cg[11]);
    u64 HX = pk(hx, hx), HY = pk(hy, hy), HZ = pk(hz, hz);

    u64 dot  = ffma2(HZ, ZC, ffma2(HY, ZB, fmul2(HX, ZA)));
    u64 smsg = ffma2(g[1], dot, fmul2(g[0], Z0));
    u64 tt   = fmul2(g[3], Z0);
    u64 vx   = ffma2(HX, tt, fmul2(g[2], ZA));
    u64 vy   = ffma2(HY, tt, fmul2(g[2], ZB));
    u64 vz   = ffma2(HZ, tt, fmul2(g[2], ZC));

    float* base = g_accP + (size_t)s * 256 + lane * 4;
    red4(base, smsg, vx);
    red4(base + 128, vy, vz);
}

__global__ __launch_bounds__(256, 3) void edge_kernel(const int* __restrict__ src,
                                                      const int* __restrict__ dst,
                                                      const float* __restrict__ r_ij) {
    const int lane = threadIdx.x & 31;
    const int warp = blockIdx.x * 8 + (threadIdx.x >> 5);
    const int nwarp = gridDim.x * 8;

    EB A, B;
    int e0 = warp, s0 = 0;
    if (e0 < NE) {
        s0 = __ldg(src + e0);
        int d0 = __ldg(dst + e0);
        float rx = __ldg(r_ij + 3 * e0), ry = __ldg(r_ij + 3 * e0 + 1), rz = __ldg(r_ij + 3 * e0 + 2);
        fill_buf(A, s0, d0, rx, ry, rz, lane);
    }
    int e1 = e0 + nwarp, s1 = 0, d1 = 0;
    float r1x = 0.f, r1y = 0.f, r1z = 0.f;
    if (e1 < NE) {
        s1 = __ldg(src + e1); d1 = __ldg(dst + e1);
        r1x = __ldg(r_ij + 3 * e1); r1y = __ldg(r_ij + 3 * e1 + 1); r1z = __ldg(r_ij + 3 * e1 + 2);
    }

    while (e0 < NE) {
        // stage 1: fill B for e1; fetch idx+r for e2; compute e0
        int e2 = e1 + nwarp, s2 = 0, d2 = 0;
        float r2x = 0.f, r2y = 0.f, r2z = 0.f;
        if (e1 < NE) fill_buf(B, s1, d1, r1x, r1y, r1z, lane);
        if (e2 < NE) {
            s2 = __ldg(src + e2); d2 = __ldg(dst + e2);
            r2x = __ldg(r_ij + 3 * e2); r2y = __ldg(r_ij + 3 * e2 + 1); r2z = __ldg(r_ij + 3 * e2 + 2);
        }
        do_edge(A, s0, lane);
        if (e1 >= NE) break;

        // stage 2: fill A for e2; fetch idx+r for e3; compute e1
        int e3 = e2 + nwarp, s3 = 0, d3 = 0;
        float r3x = 0.f, r3y = 0.f, r3z = 0.f;
        if (e2 < NE) fill_buf(A, s2, d2, r2x, r2y, r2z, lane);
        if (e3 < NE) {
            s3 = __ldg(src + e3); d3 = __ldg(dst + e3);
            r3x = __ldg(r_ij + 3 * e3); r3y = __ldg(r_ij + 3 * e3 + 1); r3z = __ldg(r_ij + 3 * e3 + 2);
        }
        do_edge(B, s1, lane);

        e0 = e2; s0 = s2;
        e1 = e3; s1 = s3; d1 = d3; r1x = r3x; r1y = r3y; r1z = r3z;
    }
}

// ---------------------------------------------------------------------------
// 5) final: out0 = acc_s @ W_s ; out1[:,i,:] = acc_v_i @ W_v
//    acc idx for (m,k): ((m>=2)?128:0) + 4*(k>>1) + ((m==1||m==3)?2:0) + (k&1)
// ---------------------------------------------------------------------------
__global__ __launch_bounds__(256) void final_kernel(const float* __restrict__ W_s,
                                                    const float* __restrict__ W_v,
                                                    float* __restrict__ out) {
    __shared__ float as[16][256];
    int base = blockIdx.x * 16;
    for (int i = threadIdx.x; i < 16 * 256; i += 256)
        as[i >> 8][i & 255] = g_accP[(size_t)base * 256 + i];
    __syncthreads();
    int o = threadIdx.x;
    int c = o & 63;
    int m = (o < 64) ? 0 : 1 + ((o - 64) >> 6);
    const float* W = (o < 64) ? W_s : W_v;
    int off = ((m >= 2) ? 128 : 0) + ((m == 1 || m == 3) ? 2 : 0);
    float a[16];
    #pragma unroll
    for (int n = 0; n < 16; n++) a[n] = 0.f;
    for (int k = 0; k < 64; k++) {
        float wv = W[k * 64 + c];
        int idx = off + 4 * (k >> 1) + (k & 1);
        #pragma unroll
        for (int n = 0; n < 16; n++) a[n] += as[n][idx] * wv;
    }
    if (m == 0) {
        #pragma unroll
        for (int n = 0; n < 16; n++) out[(base + n) * 64 + c] = a[n];
    } else {
        int i = m - 1;
        #pragma unroll
        for (int n = 0; n < 16; n++)
            out[NN * 64 + ((base + n) * 3 + i) * 64 + c] = a[n];
    }
}

// ---------------------------------------------------------------------------
extern "C" void kernel_launch(void* const* d_in, const int* in_sizes, int n_in,
                              void* d_out, int out_size) {
    const int*   src    = (const int*)d_in[0];
    const int*   dst    = (const int*)d_in[1];
    const float* r_ij   = (const float*)d_in[2];
    const float* z_0    = (const float*)d_in[3];
    const float* z_1    = (const float*)d_in[4];
    const float* emb    = (const float*)d_in[5];
    const float* W_enc  = (const float*)d_in[6];
    const float* b_enc  = (const float*)d_in[7];
    const float* W_src  = (const float*)d_in[8];
    const float* b_src  = (const float*)d_in[9];
    const float* W_dst  = (const float*)d_in[10];
    const float* b_dst  = (const float*)d_in[11];
    const float* W_gate = (const float*)d_in[12];
    const float* b_gate = (const float*)d_in[13];
    const float* W_s    = (const float*)d_in[14];
    const float* W_v    = (const float*)d_in[15];
    float* out = (float*)d_out;

    zero_convert<<<2048, 256>>>(z_0, z_1);
    prep_weights<<<137, 256>>>(W_src, W_dst, W_enc, W_gate, b_gate, b_enc, b_src, b_dst);
    table_kernel<<<(NB * 256 + 255) / 256, 256>>>();
    node_pre<<<NN / 16, 512>>>(emb);
    edge_kernel<<<888, 256>>>(src, dst, r_ij);
    final_kernel<<<NN / 16, 256>>>(W_s, W_v, out);
}